// round 6
// baseline (speedup 1.0000x reference)
#include <cuda_runtime.h>
#include <math.h>

// Problem constants
#define BB   512
#define LL   71
#define DD   512
#define HH   8
#define DHH  64
#define MROWS (BB * LL)          // 36352
#define NHEADS (BB * HH)         // 4096
#define HEAD_ELEMS (LL * DHH)    // 4544

// ---------------------------------------------------------------------------
// Scratch (static device globals)
// ---------------------------------------------------------------------------
__device__ float g_Tq[DD * MROWS];        // transposed tf32 activations [512][M]
__device__ float g_Tk[DD * MROWS];
__device__ float g_Tv[DD * MROWS];
__device__ float g_Q[NHEADS * HEAD_ELEMS]; // [bh][l][dh], Q pre-scaled by 1/8
__device__ float g_K[NHEADS * HEAD_ELEMS]; // [bh][l][dh]
__device__ float g_V[NHEADS * HEAD_ELEMS]; // [bh][l][dh]
__device__ float g_attnT[DD * MROWS];      // [d][m] tf32 (k-major for out proj)

__device__ __forceinline__ float to_tf32(float x) {
    float y;
    asm("cvt.rna.tf32.f32 %0, %1;" : "=f"(y) : "f"(x));
    return y;
}

__device__ __forceinline__ void mma_tf32(float* c, const unsigned* a, const unsigned* b) {
    asm volatile(
        "mma.sync.aligned.m16n8k8.row.col.f32.tf32.tf32.f32 "
        "{%0,%1,%2,%3}, {%4,%5,%6,%7}, {%8,%9}, {%0,%1,%2,%3};"
        : "+f"(c[0]), "+f"(c[1]), "+f"(c[2]), "+f"(c[3])
        : "r"(a[0]), "r"(a[1]), "r"(a[2]), "r"(a[3]), "r"(b[0]), "r"(b[1]));
}

__device__ __forceinline__ float gelu_exact(float x) {
    return 0.5f * x * (1.f + erff(x * 0.70710678118654752f));
}

// ---------------------------------------------------------------------------
// Transpose + tf32 convert: in [M][512] fp32 -> out [512][M] tf32.
// ---------------------------------------------------------------------------
__global__ void __launch_bounds__(256) transpose_cvt_kernel(
    const float* __restrict__ in0, const float* __restrict__ in1,
    const float* __restrict__ in2,
    float* __restrict__ out0, float* __restrict__ out1, float* __restrict__ out2)
{
    __shared__ float sm[32][33];
    const float* in = (blockIdx.z == 0) ? in0 : (blockIdx.z == 1 ? in1 : in2);
    float* out      = (blockIdx.z == 0) ? out0 : (blockIdx.z == 1 ? out1 : out2);
    const int m0 = blockIdx.x * 32, k0 = blockIdx.y * 32;
    const int tx = threadIdx.x & 31, ty = threadIdx.x >> 5;
    #pragma unroll
    for (int j = 0; j < 4; j++)
        sm[ty + 8 * j][tx] = in[(size_t)(m0 + ty + 8 * j) * 512 + k0 + tx];
    __syncthreads();
    #pragma unroll
    for (int j = 0; j < 4; j++)
        out[(size_t)(k0 + ty + 8 * j) * MROWS + m0 + tx] = to_tf32(sm[tx][ty + 8 * j]);
}

// ---------------------------------------------------------------------------
// tf32 GEMM core: CTA 128x128, K=512, KC=32, double-buffered smem.
// ---------------------------------------------------------------------------
__device__ __forceinline__ void gemm_tf32_ctile(
    const float* __restrict__ AT, const float* __restrict__ W,
    float (&c)[4][4][4])
{
    extern __shared__ float sm[];
    float* As = sm;            // [2][32][136]
    float* Bs = sm + 8704;

    const int tid  = threadIdx.x;
    const int lane = tid & 31;
    const int warp = tid >> 5;
    const int mBase = blockIdx.y * 128;
    const int nBase = blockIdx.x * 128;

    #pragma unroll
    for (int im = 0; im < 4; im++)
        #pragma unroll
        for (int in = 0; in < 4; in++)
            #pragma unroll
            for (int q = 0; q < 4; q++) c[im][in][q] = 0.f;

    auto ldgA = [&](int kt, float4 (&ra)[4]) {
        #pragma unroll
        for (int it = 0; it < 4; it++) {
            int idx = it * 256 + tid;
            int k = idx >> 5, m4 = (idx & 31) << 2;
            ra[it] = *(const float4*)(AT + (size_t)(kt * 32 + k) * MROWS + mBase + m4);
        }
    };
    auto ldgB = [&](int kt, float4 (&rb)[4]) {
        #pragma unroll
        for (int it = 0; it < 4; it++) {
            int idx = it * 256 + tid;
            int k = idx >> 5, n4 = (idx & 31) << 2;
            rb[it] = *(const float4*)(W + (size_t)(kt * 32 + k) * 512 + nBase + n4);
        }
    };
    auto stsA = [&](int buf, float4 (&ra)[4]) {
        #pragma unroll
        for (int it = 0; it < 4; it++) {
            int idx = it * 256 + tid;
            int k = idx >> 5, m4 = (idx & 31) << 2;
            *(float4*)&As[buf * 4352 + k * 136 + m4] = ra[it];
        }
    };
    auto stsB = [&](int buf, float4 (&rb)[4]) {
        #pragma unroll
        for (int it = 0; it < 4; it++) {
            int idx = it * 256 + tid;
            int k = idx >> 5, n4 = (idx & 31) << 2;
            float4 v = rb[it];
            v.x = to_tf32(v.x); v.y = to_tf32(v.y);
            v.z = to_tf32(v.z); v.w = to_tf32(v.w);
            *(float4*)&Bs[buf * 4352 + k * 136 + n4] = v;
        }
    };
    auto compute = [&](int buf) {
        const float* Asb = As + buf * 4352;
        const float* Bsb = Bs + buf * 4352;
        const int r0 = (warp & 1) * 64 + (lane >> 2);
        const int n0 = (warp >> 1) * 32 + (lane >> 2);
        #pragma unroll
        for (int s = 0; s < 4; s++) {
            const int kk = s * 8 + (lane & 3);
            unsigned a[4][4], b[4][2];
            #pragma unroll
            for (int im = 0; im < 4; im++) {
                a[im][0] = __float_as_uint(Asb[kk * 136 + r0 + im * 16]);
                a[im][1] = __float_as_uint(Asb[kk * 136 + r0 + im * 16 + 8]);
                a[im][2] = __float_as_uint(Asb[(kk + 4) * 136 + r0 + im * 16]);
                a[im][3] = __float_as_uint(Asb[(kk + 4) * 136 + r0 + im * 16 + 8]);
            }
            #pragma unroll
            for (int in = 0; in < 4; in++) {
                b[in][0] = __float_as_uint(Bsb[kk * 136 + n0 + in * 8]);
                b[in][1] = __float_as_uint(Bsb[(kk + 4) * 136 + n0 + in * 8]);
            }
            #pragma unroll
            for (int im = 0; im < 4; im++)
                #pragma unroll
                for (int in = 0; in < 4; in++)
                    mma_tf32(c[im][in], a[im], b[in]);
        }
    };

    float4 ra[4], rb[4];
    ldgA(0, ra); ldgB(0, rb);
    stsA(0, ra); stsB(0, rb);
    __syncthreads();
    #pragma unroll 1
    for (int kt = 0; kt < 16; kt++) {
        const int cur = kt & 1;
        if (kt < 15) { ldgA(kt + 1, ra); ldgB(kt + 1, rb); }
        compute(cur);
        if (kt < 15) { stsA(cur ^ 1, ra); stsB(cur ^ 1, rb); }
        __syncthreads();
    }
}

// ---------------------------------------------------------------------------
// QKV projection: grid (4, 284, 3). Coalesced float2 epilogue to [b,h,l,dh].
// ---------------------------------------------------------------------------
__global__ void __launch_bounds__(256) qkv_gemm_kernel(
    const float* __restrict__ Wq, const float* __restrict__ bq,
    const float* __restrict__ Wk, const float* __restrict__ bk,
    const float* __restrict__ Wv, const float* __restrict__ bv)
{
    const float* AT; const float* W; const float* bias; float* out; float scale;
    if (blockIdx.z == 0)      { AT = g_Tq; W = Wq; bias = bq; out = g_Q; scale = 0.125f; }
    else if (blockIdx.z == 1) { AT = g_Tk; W = Wk; bias = bk; out = g_K; scale = 1.0f; }
    else                      { AT = g_Tv; W = Wv; bias = bv; out = g_V; scale = 1.0f; }

    float c[4][4][4];
    gemm_tf32_ctile(AT, W, c);

    const int lane = threadIdx.x & 31, warp = threadIdx.x >> 5;
    const int mBase = blockIdx.y * 128, nBase = blockIdx.x * 128;

    float bv2[4][2];
    #pragma unroll
    for (int in = 0; in < 4; in++) {
        int cg = nBase + (warp >> 1) * 32 + in * 8 + 2 * (lane & 3);
        bv2[in][0] = bias[cg]; bv2[in][1] = bias[cg + 1];
    }
    #pragma unroll
    for (int im = 0; im < 4; im++) {
        int rg0 = mBase + (warp & 1) * 64 + im * 16 + (lane >> 2);
        int rg1 = rg0 + 8;
        int b0 = rg0 / 71, l0 = rg0 - b0 * 71;
        int b1 = rg1 / 71, l1 = rg1 - b1 * 71;
        #pragma unroll
        for (int in = 0; in < 4; in++) {
            int cg = nBase + (warp >> 1) * 32 + in * 8 + 2 * (lane & 3);
            int h = cg >> 6, dh = cg & 63;
            float2 v0 = make_float2((c[im][in][0] + bv2[in][0]) * scale,
                                    (c[im][in][1] + bv2[in][1]) * scale);
            float2 v1 = make_float2((c[im][in][2] + bv2[in][0]) * scale,
                                    (c[im][in][3] + bv2[in][1]) * scale);
            *(float2*)&out[(((size_t)(b0 * 8 + h) * 71 + l0) << 6) + dh] = v0;
            *(float2*)&out[(((size_t)(b1 * 8 + h) * 71 + l1) << 6) + dh] = v1;
        }
    }
}

// ---------------------------------------------------------------------------
// Output projection: grid (4, 284).
// ---------------------------------------------------------------------------
__global__ void __launch_bounds__(256) out_gemm_kernel(
    float* __restrict__ out, const float* __restrict__ Wo,
    const float* __restrict__ bo)
{
    float c[4][4][4];
    gemm_tf32_ctile(g_attnT, Wo, c);

    const int lane = threadIdx.x & 31, warp = threadIdx.x >> 5;
    const int mBase = blockIdx.y * 128, nBase = blockIdx.x * 128;

    float bv2[4][2];
    #pragma unroll
    for (int in = 0; in < 4; in++) {
        int cg = nBase + (warp >> 1) * 32 + in * 8 + 2 * (lane & 3);
        bv2[in][0] = bo[cg]; bv2[in][1] = bo[cg + 1];
    }
    #pragma unroll
    for (int im = 0; im < 4; im++) {
        int rg0 = mBase + (warp & 1) * 64 + im * 16 + (lane >> 2);
        int rg1 = rg0 + 8;
        #pragma unroll
        for (int in = 0; in < 4; in++) {
            int cg = nBase + (warp >> 1) * 32 + in * 8 + 2 * (lane & 3);
            float2 v0 = make_float2(c[im][in][0] + bv2[in][0], c[im][in][1] + bv2[in][1]);
            float2 v1 = make_float2(c[im][in][2] + bv2[in][0], c[im][in][3] + bv2[in][1]);
            *(float2*)&out[(size_t)rg0 * 512 + cg] = v0;
            *(float2*)&out[(size_t)rg1 * 512 + cg] = v1;
        }
    }
}

// ---------------------------------------------------------------------------
// Attention core stages (templated on number of N-slots, fully unrolled).
// ---------------------------------------------------------------------------

// Stage 1: S = Q @ K^T. A = sQ row-major [80][72]; B = sK [72 keys][72] (dh contig).
template<int NS>
__device__ __forceinline__ void run_stage1(
    float* __restrict__ sS, const float* __restrict__ sQ,
    const float* __restrict__ sK, int w, int lane)
{
    float acc[NS][5][4] = {};
    #pragma unroll
    for (int ks = 0; ks < 8; ks++) {
        const int cc = ks * 8 + (lane & 3);
        unsigned bfr[NS][2];
        #pragma unroll
        for (int s = 0; s < NS; s++) {
            const int n = (w + s * 8) * 8 + (lane >> 2);
            bfr[s][0] = __float_as_uint(sK[n * 72 + cc]);
            bfr[s][1] = __float_as_uint(sK[n * 72 + cc + 4]);
        }
        #pragma unroll
        for (int mt = 0; mt < 5; mt++) {
            const int r = mt * 16 + (lane >> 2);
            unsigned afr[4];
            afr[0] = __float_as_uint(sQ[r * 72 + cc]);
            afr[1] = __float_as_uint(sQ[(r + 8) * 72 + cc]);
            afr[2] = __float_as_uint(sQ[r * 72 + cc + 4]);
            afr[3] = __float_as_uint(sQ[(r + 8) * 72 + cc + 4]);
            #pragma unroll
            for (int s = 0; s < NS; s++) mma_tf32(acc[s][mt], afr, bfr[s]);
        }
    }
    #pragma unroll
    for (int s = 0; s < NS; s++) {
        const int n0 = (w + s * 8) * 8 + 2 * (lane & 3);
        #pragma unroll
        for (int mt = 0; mt < 5; mt++) {
            const int r = mt * 16 + (lane >> 2);
            sS[n0 * 88 + r]           = to_tf32(acc[s][mt][0]);
            sS[(n0 + 1) * 88 + r]     = to_tf32(acc[s][mt][1]);
            sS[n0 * 88 + r + 8]       = to_tf32(acc[s][mt][2]);
            sS[(n0 + 1) * 88 + r + 8] = to_tf32(acc[s][mt][3]);
        }
    }
}

// Stage 2: H = gelu(S @ w1 + b1). A = sS k-major [key][88]; B = w1s [key][136].
__device__ __forceinline__ void run_stage2(
    float* __restrict__ sH, const float* __restrict__ sS,
    const float* __restrict__ w1s, const float* __restrict__ b1s,
    int w, int lane)
{
    float acc[2][5][4] = {};
    #pragma unroll
    for (int ks = 0; ks < 9; ks++) {
        const int kk = ks * 8 + (lane & 3);
        unsigned bfr[2][2];
        #pragma unroll
        for (int s = 0; s < 2; s++) {
            const int n = (w + s * 8) * 8 + (lane >> 2);
            bfr[s][0] = __float_as_uint(w1s[kk * 136 + n]);
            bfr[s][1] = __float_as_uint(w1s[(kk + 4) * 136 + n]);
        }
        #pragma unroll
        for (int mt = 0; mt < 5; mt++) {
            const float* p = sS + kk * 88 + mt * 16 + (lane >> 2);
            unsigned afr[4];
            afr[0] = __float_as_uint(p[0]);
            afr[1] = __float_as_uint(p[8]);
            afr[2] = __float_as_uint(p[88 * 4]);
            afr[3] = __float_as_uint(p[88 * 4 + 8]);
            mma_tf32(acc[0][mt], afr, bfr[0]);
            mma_tf32(acc[1][mt], afr, bfr[1]);
        }
    }
    #pragma unroll
    for (int s = 0; s < 2; s++) {
        const int n0 = (w + s * 8) * 8 + 2 * (lane & 3);
        const float bb0 = b1s[n0], bb1 = b1s[n0 + 1];
        #pragma unroll
        for (int mt = 0; mt < 5; mt++) {
            const int r = mt * 16 + (lane >> 2);
            sH[n0 * 88 + r]           = to_tf32(gelu_exact(acc[s][mt][0] + bb0));
            sH[(n0 + 1) * 88 + r]     = to_tf32(gelu_exact(acc[s][mt][1] + bb1));
            sH[n0 * 88 + r + 8]       = to_tf32(gelu_exact(acc[s][mt][2] + bb0));
            sH[(n0 + 1) * 88 + r + 8] = to_tf32(gelu_exact(acc[s][mt][3] + bb1));
        }
    }
}

// Stage 3: S += H @ w2 + b2. A = sH k-major [ff][88]; B = w2s [ff][72].
template<int NS>
__device__ __forceinline__ void run_stage3(
    float* __restrict__ sS, const float* __restrict__ sH,
    const float* __restrict__ w2s, const float* __restrict__ b2s,
    int w, int lane)
{
    float acc[NS][5][4] = {};
    #pragma unroll
    for (int ks = 0; ks < 16; ks++) {
        const int kk = ks * 8 + (lane & 3);
        unsigned bfr[NS][2];
        #pragma unroll
        for (int s = 0; s < NS; s++) {
            const int n = (w + s * 8) * 8 + (lane >> 2);
            bfr[s][0] = __float_as_uint(w2s[kk * 72 + n]);
            bfr[s][1] = __float_as_uint(w2s[(kk + 4) * 72 + n]);
        }
        #pragma unroll
        for (int mt = 0; mt < 5; mt++) {
            const float* p = sH + kk * 88 + mt * 16 + (lane >> 2);
            unsigned afr[4];
            afr[0] = __float_as_uint(p[0]);
            afr[1] = __float_as_uint(p[8]);
            afr[2] = __float_as_uint(p[88 * 4]);
            afr[3] = __float_as_uint(p[88 * 4 + 8]);
            #pragma unroll
            for (int s = 0; s < NS; s++) mma_tf32(acc[s][mt], afr, bfr[s]);
        }
    }
    #pragma unroll
    for (int s = 0; s < NS; s++) {
        const int n0 = (w + s * 8) * 8 + 2 * (lane & 3);
        const float bb0 = b2s[n0], bb1 = b2s[n0 + 1];
        #pragma unroll
        for (int mt = 0; mt < 5; mt++) {
            const int r = mt * 16 + (lane >> 2);
            sS[n0 * 88 + r]           += acc[s][mt][0] + bb0;
            sS[(n0 + 1) * 88 + r]     += acc[s][mt][1] + bb1;
            sS[n0 * 88 + r + 8]       += acc[s][mt][2] + bb0;
            sS[(n0 + 1) * 88 + r + 8] += acc[s][mt][3] + bb1;
        }
    }
}

// ---------------------------------------------------------------------------
// Tensorized attention core. CTA = 2 heads (512 thr). Grid = 2048.
// Per-head (17600 floats): sS [72][88] at +0; union U at +6336:
//   stage0-1: sQ [80][72] + sK [72][72]; stage2-3: sH [128][88]; stage5: sV [72][72].
// Shared at 35200: w1s [72][136], w2s [128][72], b1s[128], b2s[72].
// ---------------------------------------------------------------------------
__global__ void __launch_bounds__(512) attn_kernel(
    const float* __restrict__ w1, const float* __restrict__ b1,
    const float* __restrict__ w2, const float* __restrict__ b2)
{
    extern __shared__ float sm[];
    const int tid  = threadIdx.x;
    const int lane = tid & 31;
    const int warp = tid >> 5;      // 0..15
    const int half = warp >> 3;     // 0/1
    const int w    = warp & 7;      // 0..7
    const int htid = tid & 255;
    const int bh   = blockIdx.x * 2 + half;
    const int bidx = bh >> 3, hidx = bh & 7;

    float* sS  = sm + half * 17600;
    float* U   = sS + 6336;
    float* w1s = sm + 35200;
    float* w2s = w1s + 9792;
    float* b1s = w2s + 9216;
    float* b2s = b1s + 128;

    // ---- shared weight loads (all 512 threads) ----
    for (int i = tid; i < 72 * 128; i += 512) {
        int k = i >> 7, n = i & 127;
        w1s[k * 136 + n] = (k < 71) ? to_tf32(w1[k * 128 + n]) : 0.f;
    }
    for (int i = tid; i < 128 * 72; i += 512) {
        int k = i / 72, n = i - k * 72;
        w2s[k * 72 + n] = (n < 71) ? to_tf32(w2[k * 71 + n]) : 0.f;
    }
    if (tid < 128) b1s[tid] = b1[tid];
    if (tid < 72)  b2s[tid] = (tid < 71) ? b2[tid] : 0.f;

    // ---- load Q, K natural [l][dh] (coalesced LDG, consecutive-bank STS) ----
    {
        float* sQ = U;            // [80][72]
        float* sK = U + 5760;     // [72][72]
        const float* Qg = g_Q + (size_t)bh * HEAD_ELEMS;
        const float* Kg = g_K + (size_t)bh * HEAD_ELEMS;
        for (int i = htid; i < HEAD_ELEMS; i += 256) {
            int l = i >> 6, dh = i & 63;
            sQ[l * 72 + dh] = to_tf32(Qg[i]);
            sK[l * 72 + dh] = to_tf32(Kg[i]);
        }
        for (int i = htid; i < 9 * 72; i += 256) sQ[71 * 72 + i] = 0.f; // rows 71..79
        if (htid < 72) sK[71 * 72 + htid] = 0.f;                        // pad key row
    }
    __syncthreads();

    // ---- stage 1: S = Q @ K^T -> sS[key][query] ----
    if (w == 0) run_stage1<2>(sS, U, U + 5760, w, lane);
    else        run_stage1<1>(sS, U, U + 5760, w, lane);
    __syncthreads();

    // ---- stage 2: H = gelu(S @ w1 + b1) -> sH[ff][query] (overwrites Q/K) ----
    run_stage2(U, sS, w1s, b1s, w, lane);
    __syncthreads();

    // ---- stage 3: S += H @ w2 + b2 ----
    if (w == 0) run_stage3<2>(sS, U, w2s, b2s, w, lane);
    else        run_stage3<1>(sS, U, w2s, b2s, w, lane);
    __syncthreads();

    // ---- V load into U (overwrites dead sH) + softmax on sS columns ----
    {
        float* sV = U;           // [72][72]
        const float* Vg = g_V + (size_t)bh * HEAD_ELEMS;
        for (int i = htid; i < HEAD_ELEMS; i += 256) {
            int l = i >> 6, dh = i & 63;
            sV[l * 72 + dh] = to_tf32(Vg[i]);
        }
        if (htid < 72) sV[71 * 72 + htid] = 0.f;   // pad key row (P row is 0 anyway)
    }
    if (htid < 71) {
        const int q = htid;
        float mx = -1e30f;
        #pragma unroll 1
        for (int k = 0; k < 71; k++) mx = fmaxf(mx, sS[k * 88 + q]);
        float ssum = 0.f;
        #pragma unroll 1
        for (int k = 0; k < 71; k++) {
            float e = __expf(sS[k * 88 + q] - mx);
            sS[k * 88 + q] = e;
            ssum += e;
        }
        float inv = 1.f / ssum;
        #pragma unroll 1
        for (int k = 0; k < 71; k++) sS[k * 88 + q] = to_tf32(sS[k * 88 + q] * inv);
    }
    __syncthreads();

    // ---- stage 5: attn = P @ V -> g_attnT[d][m] ----
    {
        const float* sV = U;
        float acc[5][4] = {};
        #pragma unroll
        for (int ks = 0; ks < 9; ks++) {
            const int kk = ks * 8 + (lane & 3);
            unsigned bfr[2];
            const int n = w * 8 + (lane >> 2);
            bfr[0] = __float_as_uint(sV[kk * 72 + n]);
            bfr[1] = __float_as_uint(sV[(kk + 4) * 72 + n]);
            #pragma unroll
            for (int mt = 0; mt < 5; mt++) {
                const float* p = sS + kk * 88 + mt * 16 + (lane >> 2);
                unsigned afr[4];
                afr[0] = __float_as_uint(p[0]);
                afr[1] = __float_as_uint(p[8]);
                afr[2] = __float_as_uint(p[88 * 4]);
                afr[3] = __float_as_uint(p[88 * 4 + 8]);
                mma_tf32(acc[mt], afr, bfr);
            }
        }
        const int n0 = w * 8 + 2 * (lane & 3);
        const size_t d0 = (size_t)(hidx * 64 + n0);
        #pragma unroll
        for (int mt = 0; mt < 5; mt++) {
            int r = mt * 16 + (lane >> 2);
            if (r < 71) {
                size_t mg = (size_t)bidx * 71 + r;
                g_attnT[d0 * MROWS + mg]       = to_tf32(acc[mt][0]);
                g_attnT[(d0 + 1) * MROWS + mg] = to_tf32(acc[mt][1]);
            }
            if (r + 8 < 71) {
                size_t mg = (size_t)bidx * 71 + r + 8;
                g_attnT[d0 * MROWS + mg]       = to_tf32(acc[mt][2]);
                g_attnT[(d0 + 1) * MROWS + mg] = to_tf32(acc[mt][3]);
            }
        }
    }
}

// ---------------------------------------------------------------------------
extern "C" void kernel_launch(void* const* d_in, const int* in_sizes, int n_in,
                              void* d_out, int out_size)
{
    const float* query = (const float*)d_in[0];
    const float* key   = (const float*)d_in[1];
    const float* value = (const float*)d_in[2];
    const float* Wq = (const float*)d_in[3];
    const float* bq = (const float*)d_in[4];
    const float* Wk = (const float*)d_in[5];
    const float* bk = (const float*)d_in[6];
    const float* Wv = (const float*)d_in[7];
    const float* bv = (const float*)d_in[8];
    const float* Wo = (const float*)d_in[9];
    const float* bo = (const float*)d_in[10];
    const float* sf_w1 = (const float*)d_in[11];
    const float* sf_b1 = (const float*)d_in[12];
    const float* sf_w2 = (const float*)d_in[13];
    const float* sf_b2 = (const float*)d_in[14];
    float* out = (float*)d_out;

    float *dTq, *dTk, *dTv;
    cudaGetSymbolAddress((void**)&dTq, g_Tq);
    cudaGetSymbolAddress((void**)&dTk, g_Tk);
    cudaGetSymbolAddress((void**)&dTv, g_Tv);

    const int gemm_smem = 17408 * sizeof(float);    // 69632 B
    cudaFuncSetAttribute(qkv_gemm_kernel, cudaFuncAttributeMaxDynamicSharedMemorySize, gemm_smem);
    cudaFuncSetAttribute(out_gemm_kernel, cudaFuncAttributeMaxDynamicSharedMemorySize, gemm_smem);
    const int attn_smem = 54408 * sizeof(float);    // 217632 B
    cudaFuncSetAttribute(attn_kernel, cudaFuncAttributeMaxDynamicSharedMemorySize, attn_smem);

    // 1) transpose+cvt activations
    dim3 gt(MROWS / 32, 16, 3);
    transpose_cvt_kernel<<<gt, 256>>>(query, key, value, dTq, dTk, dTv);

    // 2) QKV projections (tf32 tensor cores)
    dim3 g1(4, 284, 3);
    qkv_gemm_kernel<<<g1, 256, gemm_smem>>>(Wq, bq, Wk, bk, Wv, bv);

    // 3) tensorized attention core (2 heads per CTA)
    attn_kernel<<<NHEADS / 2, 512, attn_smem>>>(sf_w1, sf_b1, sf_w2, sf_b2);

    // 4) output projection
    dim3 g3(4, 284);
    out_gemm_kernel<<<g3, 256, gemm_smem>>>(out, Wo, bo);
}